// round 1
// baseline (speedup 1.0000x reference)
#include <cuda_runtime.h>
#include <math.h>

// Attentional Factorization Machine, fused single-kernel fp32 implementation.
//
// Math (per batch b):
//   V[f]   = emb_v[x[f,b]]                         (32 x 64)
//   For each pair (i<j):  VV = V[i]*V[j]           (64)
//     hid   = relu(VV @ W + at_b)                  (64)
//     score = hid . at_h
//     s1    = VV . p
//     total += score * s1        <-- pooled@p collapses to a scalar!
//   out[b] = sigmoid(total + w0 + sum_f w1[x[f,b]])
//
// Design: 1 CTA per batch element, 8 warps, 62 pairs per warp.
//  - W (64x64) lives in REGISTERS: lane owns columns h=lane and h=lane+32,
//    packed along k as f32x2 (64 u64 regs). Avoids the per-pair 16KB smem
//    W traffic that would make this crossbar-bound.
//  - VV packed along k in smem (double-buffered per warp), broadcast LDS.64
//    in the inner loop feeds fma.rn.f32x2 directly (2 MACs/instr, no packing).
//  - Inner loop: 32 x (1 LDS.64 bcast + 2 FFMA2) per pair -> FMA-pipe bound.

#define F      32
#define BSZ    2048
#define KD     64
#define HD     64
#define NPAIR  496
#define NTHR   256
#define NWARP  8

typedef unsigned long long u64;

__device__ __forceinline__ u64 pack2(float lo, float hi) {
    u64 r; asm("mov.b64 %0, {%1, %2};" : "=l"(r) : "f"(lo), "f"(hi)); return r;
}
__device__ __forceinline__ void unpack2(u64 v, float& lo, float& hi) {
    asm("mov.b64 {%0, %1}, %2;" : "=f"(lo), "=f"(hi) : "l"(v));
}
__device__ __forceinline__ u64 mul2(u64 a, u64 b) {
    u64 r; asm("mul.rn.f32x2 %0, %1, %2;" : "=l"(r) : "l"(a), "l"(b)); return r;
}
#define FFMA2(acc, a, b) asm("fma.rn.f32x2 %0, %1, %2, %0;" : "+l"(acc) : "l"(a), "l"(b))

__global__ __launch_bounds__(NTHR, 1)
void afm_kernel(const int* __restrict__ x, const float* __restrict__ emb_v,
                const float* __restrict__ at_w, const float* __restrict__ at_b,
                const float* __restrict__ at_h, const float* __restrict__ p,
                const float* __restrict__ w0, const float* __restrict__ w1,
                float* __restrict__ out)
{
    __shared__ float sV[F * KD];              // 8 KB: V rows for this batch
    __shared__ u64   sVV[NWARP][2][KD / 2];   // 4 KB: per-warp vv, double-buffered
    __shared__ int   sPair[NPAIR];            // 2 KB: packed (i<<8)|j
    __shared__ int   sX[F];
    __shared__ float sTot[NWARP];
    __shared__ float sFm1;

    const int b    = blockIdx.x;
    const int tid  = threadIdx.x;
    const int w    = tid >> 5;
    const int lane = tid & 31;

    if (tid < F) sX[tid] = x[tid * BSZ + b];
    __syncthreads();

    // Embedding gather: 32 fields x 64 dims (coalesced 256B per field row)
    for (int idx = tid; idx < F * KD; idx += NTHR) {
        int f = idx >> 6, k = idx & 63;
        sV[idx] = emb_v[(long long)sX[f] * KD + k];
    }
    // Pair table (i<j lexicographic, matching np.triu_indices(F, k=1))
    for (int q = tid; q < NPAIR; q += NTHR) {
        int i = 0, r = q;
        while (r >= F - 1 - i) { r -= F - 1 - i; i++; }
        sPair[q] = (i << 8) | (i + 1 + r);
    }
    // First-order FM part (warp 0; F == 32 == warp size)
    if (w == 0) {
        float v = w1[sX[lane]];
        #pragma unroll
        for (int off = 16; off; off >>= 1) v += __shfl_xor_sync(0xffffffffu, v, off);
        if (lane == 0) sFm1 = v + w0[0];
    }

    // W into registers: lane owns h0=lane, h1=lane+32; packed along k:
    // Wr*[j] = { W[2j][h], W[2j+1][h] } to match vv2 = { vv[2j], vv[2j+1] }.
    u64 Wr0[32], Wr1[32];
    const int h0 = lane, h1 = lane + 32;
    #pragma unroll
    for (int j = 0; j < 32; j++) {
        Wr0[j] = pack2(at_w[(2 * j) * HD + h0], at_w[(2 * j + 1) * HD + h0]);
        Wr1[j] = pack2(at_w[(2 * j) * HD + h1], at_w[(2 * j + 1) * HD + h1]);
    }
    const float bl0 = at_b[h0], bl1 = at_b[h1];
    const float ah0 = at_h[h0], ah1 = at_h[h1];
    const float2 pl = ((const float2*)p)[lane];   // { p[2l], p[2l+1] }
    const u64 p2 = pack2(pl.x, pl.y);

    __syncthreads();

    float total = 0.f;
    for (int q = w; q < NPAIR; q += NWARP) {
        const int pr = sPair[q];
        const int i = pr >> 8, j = pr & 255;

        // vv packed along k: lane l produces { vv[2l], vv[2l+1] }
        const u64 vi2 = ((const u64*)(sV + i * KD))[lane];
        const u64 vj2 = ((const u64*)(sV + j * KD))[lane];
        const u64 vv2 = mul2(vi2, vj2);
        const int buf = (q >> 3) & 1;
        sVV[w][buf][lane] = vv2;

        // s1 = VV . p partial (packed mul, horizontal add, reduced later)
        const u64 s1v = mul2(vv2, p2);
        float s1lo, s1hi; unpack2(s1v, s1lo, s1hi);
        float s1part = s1lo + s1hi;

        __syncwarp();   // vv visible to all lanes; also fences prev buffer reuse

        // hid[h0], hid[h1]: 32 broadcast LDS.64 + 64 FFMA2 (2 MACs each)
        u64 acc0 = 0ull, acc1 = 0ull;
        const u64* vv = &sVV[w][buf][0];
        #pragma unroll
        for (int jj = 0; jj < 32; jj++) {
            const u64 v = vv[jj];
            FFMA2(acc0, v, Wr0[jj]);
            FFMA2(acc1, v, Wr1[jj]);
        }
        float a0l, a0h, a1l, a1h;
        unpack2(acc0, a0l, a0h); unpack2(acc1, a1l, a1h);
        const float hh0 = fmaxf(a0l + a0h + bl0, 0.f);
        const float hh1 = fmaxf(a1l + a1h + bl1, 0.f);
        float sc = hh0 * ah0 + hh1 * ah1;

        // joint warp reduction of score and s1
        #pragma unroll
        for (int off = 16; off; off >>= 1) {
            sc     += __shfl_xor_sync(0xffffffffu, sc, off);
            s1part += __shfl_xor_sync(0xffffffffu, s1part, off);
        }
        total = fmaf(sc, s1part, total);
    }

    if (lane == 0) sTot[w] = total;
    __syncthreads();
    if (tid == 0) {
        float t = sFm1;
        #pragma unroll
        for (int k = 0; k < NWARP; k++) t += sTot[k];
        out[b] = 1.f / (1.f + expf(-t));
    }
}

extern "C" void kernel_launch(void* const* d_in, const int* in_sizes, int n_in,
                              void* d_out, int out_size)
{
    (void)in_sizes; (void)n_in; (void)out_size;
    afm_kernel<<<BSZ, NTHR>>>(
        (const int*)  d_in[0],   // x        [F, B] int32
        (const float*)d_in[1],   // emb_v    [VOCAB, K]
        (const float*)d_in[2],   // at_w     [K, H]
        (const float*)d_in[3],   // at_b     [H]
        (const float*)d_in[4],   // at_h     [H, 1]
        (const float*)d_in[5],   // p        [K, 1]
        (const float*)d_in[6],   // w0       scalar
        (const float*)d_in[7],   // w1       [VOCAB, 1]
        (float*)d_out);          // prob     [B, 1] float32
}

// round 4
// speedup vs baseline: 4.4918x; 4.4918x over previous
#include <cuda_runtime.h>
#include <cuda_bf16.h>
#include <cstdint>
#include <math.h>

// AFM fused kernel using mma.sync.m16n8k16 bf16 (plain-sm_103-safe HMMA path).
//
// Per batch b (one CTA, 8 warps):
//   V = emb_v[x[:,b]]                       (32 x 64 fp32, smem)
//   warp w owns 62 pairs -> 4 m-tiles of 16 rows
//   VV (bf16) @ B^T where B = [W^T (64 rows); p (1 row); 0 pad] -> N=72
//     D[:,0:64] = hid pre-act, D[:,64] = s1 = VV.p   (s1 free inside the GEMM)
//   score = sum_h relu(D+b)*ah ; total += score * s1   (quad-shuffle reduce only)
//   out[b] = sigmoid(total + w0 + sum_f w1[x[f,b]])    (fm1 exact fp32 - dominates)

#define F      32
#define BSZ    2048
#define KD     64
#define HD     64
#define NPAIR  496
#define NTHR   256
#define PPW    62          // pairs per warp
#define VSTR   144         // smem row stride (bytes) -> conflict-free frag loads
#define NB     72          // GEMM N: 64 hid + 1 s1 + 7 pad

__device__ __forceinline__ float reluf(float v) { return fmaxf(v, 0.f); }

#define MMA16816(d, a, bb)                                                      \
    asm volatile("mma.sync.aligned.m16n8k16.row.col.f32.bf16.bf16.f32 "         \
                 "{%0,%1,%2,%3}, {%4,%5,%6,%7}, {%8,%9}, {%0,%1,%2,%3};"        \
                 : "+f"((d)[0]), "+f"((d)[1]), "+f"((d)[2]), "+f"((d)[3])       \
                 : "r"((a)[0]), "r"((a)[1]), "r"((a)[2]), "r"((a)[3]),          \
                   "r"((bb)[0]), "r"((bb)[1]))

// pack two fp32 -> bf16x2 (lo -> low half)
#define PACKBF2(res, flo, fhi) \
    asm("cvt.rn.bf16x2.f32 %0, %1, %2;" : "=r"(res) : "f"(fhi), "f"(flo))

__global__ __launch_bounds__(NTHR)
void afm_hmma_kernel(const int* __restrict__ x, const float* __restrict__ emb_v,
                     const float* __restrict__ at_w, const float* __restrict__ at_b,
                     const float* __restrict__ at_h, const float* __restrict__ p,
                     const float* __restrict__ w0, const float* __restrict__ w1,
                     float* __restrict__ out)
{
    __shared__ float sV[F][KD];                            // 8 KB
    __shared__ __align__(16) unsigned char sVV[8 * 16 * VSTR]; // 18 KB, per-warp 16 rows
    __shared__ __align__(16) unsigned char sB[NB * VSTR];  // 10.1 KB: [Wt; p; 0] bf16
    __shared__ float2 sBH[HD];                             // (bias, at_h)
    __shared__ int   sPair[NPAIR];
    __shared__ int   sX[F];
    __shared__ float sTot[8];
    __shared__ float sFm1;

    const int b = blockIdx.x, tid = threadIdx.x;
    const int w = tid >> 5, lane = tid & 31;
    const int g = lane >> 2, q4 = lane & 3;   // fragment group / quad index

    if (tid < F) sX[tid] = x[tid * BSZ + b];
    __syncthreads();

    // embedding gather, float4-coalesced (32 rows x 256B)
    for (int idx = tid; idx < F * KD / 4; idx += NTHR) {
        int f = idx >> 4, c = idx & 15;
        ((float4*)sV[f])[c] = ((const float4*)(emb_v + (size_t)sX[f] * KD))[c];
    }
    // B tile rows 0..63 = W^T (row h, k contiguous bf16), row 64 = p, 65..71 = 0
    for (int idx = tid; idx < KD * HD; idx += NTHR) {
        int k = idx >> 6, h = idx & 63;
        *(__nv_bfloat16*)(sB + h * VSTR + k * 2) = __float2bfloat16(at_w[idx]);
    }
    if (tid < KD)
        *(__nv_bfloat16*)(sB + 64 * VSTR + tid * 2) = __float2bfloat16(p[tid]);
    for (int idx = tid; idx < 7 * (VSTR / 4); idx += NTHR) {
        int row = 65 + idx / (VSTR / 4), c = idx % (VSTR / 4);
        *(uint32_t*)(sB + row * VSTR + c * 4) = 0u;
    }
    if (tid < HD) sBH[tid] = make_float2(at_b[tid], at_h[tid]);
    for (int q = tid; q < NPAIR; q += NTHR) {
        int i = 0, r = q;
        while (r >= F - 1 - i) { r -= F - 1 - i; i++; }
        sPair[q] = (i << 8) | (i + 1 + r);
    }
    if (w == 7) {  // first-order FM, exact fp32
        float v = w1[sX[lane]];
        #pragma unroll
        for (int off = 16; off; off >>= 1) v += __shfl_xor_sync(0xffffffffu, v, off);
        if (lane == 0) sFm1 = v + w0[0];
    }
    __syncthreads();

    // ---- B fragments in registers (once): Bf[ntile][kstep][2] ----
    uint32_t Bf[9][4][2];
    #pragma unroll
    for (int nt = 0; nt < 9; nt++)
        #pragma unroll
        for (int ks = 0; ks < 4; ks++) {
            const unsigned char* base = sB + (nt * 8 + g) * VSTR + ks * 32 + q4 * 4;
            Bf[nt][ks][0] = *(const uint32_t*)(base);
            Bf[nt][ks][1] = *(const uint32_t*)(base + 16);
        }

    unsigned char* sVVw = sVV + w * 16 * VSTR;
    const int qbase = w * PPW;
    float acc = 0.f;

    #pragma unroll
    for (int mt = 0; mt < 4; mt++) {
        // build 16 VV rows (lane owns k = 2*lane, 2*lane+1)
        #pragma unroll
        for (int rr = 0; rr < 16; rr++) {
            const int q = qbase + mt * 16 + rr;
            uint32_t* dst = (uint32_t*)(sVVw + rr * VSTR + lane * 4);
            if (mt * 16 + rr < PPW) {
                const int pr = sPair[q];
                const float2 a = ((const float2*)sV[pr >> 8])[lane];
                const float2 c = ((const float2*)sV[pr & 255])[lane];
                uint32_t pk; PACKBF2(pk, a.x * c.x, a.y * c.y);
                *dst = pk;
            } else *dst = 0u;
        }
        __syncwarp();

        // A fragments: rows g, g+8; k bytes ks*32 + q4*4 (+16 for k+8)
        uint32_t Af[4][4];
        #pragma unroll
        for (int ks = 0; ks < 4; ks++) {
            const unsigned char* r0 = sVVw + g * VSTR + ks * 32 + q4 * 4;
            const unsigned char* r1 = r0 + 8 * VSTR;
            Af[ks][0] = *(const uint32_t*)(r0);
            Af[ks][1] = *(const uint32_t*)(r1);
            Af[ks][2] = *(const uint32_t*)(r0 + 16);
            Af[ks][3] = *(const uint32_t*)(r1 + 16);
        }
        __syncwarp();   // frags in regs; smem free for next m-tile

        float sc0 = 0.f, sc1 = 0.f, s1a = 0.f, s1b = 0.f;
        #pragma unroll
        for (int nt = 0; nt < 9; nt++) {
            float d[4] = {0.f, 0.f, 0.f, 0.f};
            #pragma unroll
            for (int ks = 0; ks < 4; ks++) MMA16816(d, Af[ks], Bf[nt][ks]);
            if (nt < 8) {
                const int c = nt * 8 + q4 * 2;
                const float2 bh0 = sBH[c], bh1 = sBH[c + 1];
                sc0 += reluf(d[0] + bh0.x) * bh0.y + reluf(d[1] + bh1.x) * bh1.y;
                sc1 += reluf(d[2] + bh0.x) * bh0.y + reluf(d[3] + bh1.x) * bh1.y;
            } else if (q4 == 0) { s1a = d[0]; s1b = d[2]; }
        }
        // quad reduction (cols) -> rows g, g+8 totals on q4==0
        sc0 += __shfl_xor_sync(0xffffffffu, sc0, 1);
        sc0 += __shfl_xor_sync(0xffffffffu, sc0, 2);
        sc1 += __shfl_xor_sync(0xffffffffu, sc1, 1);
        sc1 += __shfl_xor_sync(0xffffffffu, sc1, 2);
        if (q4 == 0) acc = fmaf(sc0, s1a, fmaf(sc1, s1b, acc));
    }

    // warp total (non-q4==0 lanes hold 0)
    #pragma unroll
    for (int off = 16; off; off >>= 1) acc += __shfl_xor_sync(0xffffffffu, acc, off);
    if (lane == 0) sTot[w] = acc;
    __syncthreads();
    if (tid == 0) {
        float t = sFm1;
        #pragma unroll
        for (int k = 0; k < 8; k++) t += sTot[k];
        out[b] = 1.f / (1.f + expf(-t));
    }
}

extern "C" void kernel_launch(void* const* d_in, const int* in_sizes, int n_in,
                              void* d_out, int out_size)
{
    (void)in_sizes; (void)n_in; (void)out_size;
    afm_hmma_kernel<<<BSZ, NTHR>>>(
        (const int*)  d_in[0],   // x      [F, B]
        (const float*)d_in[1],   // emb_v  [VOCAB, K]
        (const float*)d_in[2],   // at_w   [K, H]
        (const float*)d_in[3],   // at_b   [H]
        (const float*)d_in[4],   // at_h   [H, 1]
        (const float*)d_in[5],   // p      [K, 1]
        (const float*)d_in[6],   // w0     scalar
        (const float*)d_in[7],   // w1     [VOCAB, 1]
        (float*)d_out);
}

// round 5
// speedup vs baseline: 5.6073x; 1.2483x over previous
#include <cuda_runtime.h>
#include <cuda_bf16.h>
#include <cstdint>
#include <math.h>

// AFM fused dual-GEMM kernel (mma.sync m16n8k16 bf16, plain-sm_103 PTX).
//
// GEMM1: D = VV[16p x 64] @ B^T, B = [W^T(64); p(1); 0(7)] -> N=72
//        D[:,0:64] = hid pre-act, D[:,64] = s1 = VV.p
// GEMM2: score = relu(D[:,0:64]+bias) @ at_h   (D-frag -> A-frag, same thread!)
// acc  += score_g * s1_g   on q4==0 lanes (others are exactly 0*0)
// out[b] = sigmoid(Σacc + w0 + Σ w1[x[:,b]])   (fm1 exact fp32)
//
// 8 warps, each owns 64 pair-rows (496 real + 16 dummy (32,32)->zero row).
// 2 batch elements per CTA; B fragments live in regs across both.

#define F      32
#define BSZ    2048
#define KD     64
#define NPAIR  496
#define NPAD   512
#define NTHR   256
#define NBATCH 2
#define BSTR   144          // sB row stride (bytes)
#define VROW   68           // sV row stride (floats): 16B-aligned, bank-spread
#define VNB    (33 * VROW)  // per-batch sV floats (33 rows: 32 fields + zero row)

#define MMA16816(d, a, bb)                                                      \
    asm volatile("mma.sync.aligned.m16n8k16.row.col.f32.bf16.bf16.f32 "         \
                 "{%0,%1,%2,%3}, {%4,%5,%6,%7}, {%8,%9}, {%0,%1,%2,%3};"        \
                 : "+f"((d)[0]), "+f"((d)[1]), "+f"((d)[2]), "+f"((d)[3])       \
                 : "r"((a)[0]), "r"((a)[1]), "r"((a)[2]), "r"((a)[3]),          \
                   "r"((bb)[0]), "r"((bb)[1]))

// pack two fp32 -> bf16x2 (flo -> low half)
#define PACKBF2(res, flo, fhi) \
    asm("cvt.rn.bf16x2.f32 %0, %1, %2;" : "=r"(res) : "f"(fhi), "f"(flo))

__global__ __launch_bounds__(NTHR, 2)
void afm_dual_kernel(const int* __restrict__ x, const float* __restrict__ emb_v,
                     const float* __restrict__ at_w, const float* __restrict__ at_b,
                     const float* __restrict__ at_h, const float* __restrict__ p,
                     const float* __restrict__ w0, const float* __restrict__ w1,
                     float* __restrict__ out)
{
    __shared__ __align__(16) float sV[NBATCH * VNB];            // ~18 KB
    __shared__ __align__(16) unsigned char sB[72 * BSTR];       // ~10 KB
    __shared__ float sBias[KD];
    __shared__ int   sPair[NPAD];
    __shared__ int   sX[NBATCH][F];
    __shared__ float sTot[NBATCH][8];
    __shared__ float sFm1[NBATCH];

    const int b0 = blockIdx.x * NBATCH, tid = threadIdx.x;
    const int w = tid >> 5, lane = tid & 31;
    const int g = lane >> 2, q4 = lane & 3;

    if (tid < NBATCH * F) sX[tid >> 5][tid & 31] = x[(tid & 31) * BSZ + b0 + (tid >> 5)];
    __syncthreads();

    // V gather (float4-coalesced), rows padded to VROW
    for (int idx = tid; idx < NBATCH * F * 16; idx += NTHR) {
        const int nb = idx >> 9, rem = idx & 511, f = rem >> 4, c = rem & 15;
        ((float4*)(sV + nb * VNB + f * VROW))[c] =
            ((const float4*)(emb_v + (size_t)sX[nb][f] * KD))[c];
    }
    if (tid < NBATCH * KD) sV[(tid >> 6) * VNB + 32 * VROW + (tid & 63)] = 0.f;  // zero row

    // sB rows 0..63 = W^T, row 64 = p, rows 65..71 = 0
    for (int idx = tid; idx < KD * KD; idx += NTHR) {
        const int k = idx >> 6, h = idx & 63;
        *(__nv_bfloat16*)(sB + h * BSTR + k * 2) = __float2bfloat16(at_w[idx]);
    }
    if (tid < KD) *(__nv_bfloat16*)(sB + 64 * BSTR + tid * 2) = __float2bfloat16(p[tid]);
    for (int idx = tid; idx < 7 * (BSTR / 4); idx += NTHR) {
        const int row = 65 + idx / (BSTR / 4), c = idx % (BSTR / 4);
        *(uint32_t*)(sB + row * BSTR + c * 4) = 0u;
    }
    if (tid < KD) sBias[tid] = at_b[tid];
    for (int q = tid; q < NPAD; q += NTHR) {
        if (q < NPAIR) {
            int i = 0, r = q;
            while (r >= F - 1 - i) { r -= F - 1 - i; i++; }
            sPair[q] = (i << 8) | (i + 1 + r);
        } else sPair[q] = (32 << 8) | 32;     // dummy -> zero VV -> s1=0
    }
    if (w >= 8 - NBATCH) {                    // fm1 exact fp32 (dominates logit)
        const int nb = 7 - w;
        float v = w1[sX[nb][lane]];
        #pragma unroll
        for (int off = 16; off; off >>= 1) v += __shfl_xor_sync(0xffffffffu, v, off);
        if (lane == 0) sFm1[nb] = v + w0[0];
    }
    __syncthreads();

    // B fragments for GEMM1 (nt 0..7), held across both batches
    uint32_t Bf[8][4][2];
    #pragma unroll
    for (int nt = 0; nt < 8; nt++)
        #pragma unroll
        for (int ks = 0; ks < 4; ks++) {
            const unsigned char* base = sB + (nt * 8 + g) * BSTR + ks * 32 + q4 * 4;
            Bf[nt][ks][0] = *(const uint32_t*)(base);
            Bf[nt][ks][1] = *(const uint32_t*)(base + 16);
        }
    // GEMM2 B fragments: col 0 = at_h, cols 1..7 = 0
    uint32_t Bh[4][2];
    #pragma unroll
    for (int ks = 0; ks < 4; ks++) {
        if (g == 0) {
            const int k0 = ks * 16 + 2 * q4;
            PACKBF2(Bh[ks][0], at_h[k0], at_h[k0 + 1]);
            PACKBF2(Bh[ks][1], at_h[k0 + 8], at_h[k0 + 9]);
        } else { Bh[ks][0] = 0u; Bh[ks][1] = 0u; }
    }

    float accv[NBATCH];
    #pragma unroll 1
    for (int nb = 0; nb < NBATCH; nb++) {
        const float* sVn = sV + nb * VNB;
        float acc = 0.f;
        #pragma unroll
        for (int mt = 0; mt < 4; mt++) {
            const int q0 = w * 64 + mt * 16 + g;
            const int pr0 = sPair[q0], pr1 = sPair[q0 + 8];
            const float* pi0 = sVn + (pr0 >> 8) * VROW;
            const float* pj0 = sVn + (pr0 & 255) * VROW;
            const float* pi1 = sVn + (pr1 >> 8) * VROW;
            const float* pj1 = sVn + (pr1 & 255) * VROW;

            // A fragments straight into registers (no smem round trip)
            uint32_t Af[4][4];
            #pragma unroll
            for (int ks = 0; ks < 4; ks++) {
                const int k0 = ks * 16 + 2 * q4;
                float2 a, b2;
                a = *(const float2*)(pi0 + k0); b2 = *(const float2*)(pj0 + k0);
                PACKBF2(Af[ks][0], a.x * b2.x, a.y * b2.y);
                a = *(const float2*)(pi1 + k0); b2 = *(const float2*)(pj1 + k0);
                PACKBF2(Af[ks][1], a.x * b2.x, a.y * b2.y);
                a = *(const float2*)(pi0 + k0 + 8); b2 = *(const float2*)(pj0 + k0 + 8);
                PACKBF2(Af[ks][2], a.x * b2.x, a.y * b2.y);
                a = *(const float2*)(pi1 + k0 + 8); b2 = *(const float2*)(pj1 + k0 + 8);
                PACKBF2(Af[ks][3], a.x * b2.x, a.y * b2.y);
            }

            // GEMM1: hid (nt 0..7) + s1 (nt 8, B-frag from smem to save regs)
            uint32_t hp[8][2];
            float s1a, s1b;
            #pragma unroll
            for (int nt = 0; nt < 9; nt++) {
                float d[4] = {0.f, 0.f, 0.f, 0.f};
                if (nt < 8) {
                    #pragma unroll
                    for (int ks = 0; ks < 4; ks++) MMA16816(d, Af[ks], Bf[nt][ks]);
                    const float2 bc = *(const float2*)(sBias + nt * 8 + 2 * q4);
                    const float d0 = fmaxf(d[0] + bc.x, 0.f), d1 = fmaxf(d[1] + bc.y, 0.f);
                    const float d2 = fmaxf(d[2] + bc.x, 0.f), d3 = fmaxf(d[3] + bc.y, 0.f);
                    PACKBF2(hp[nt][0], d0, d1);
                    PACKBF2(hp[nt][1], d2, d3);
                } else {
                    #pragma unroll
                    for (int ks = 0; ks < 4; ks++) {
                        const unsigned char* bs = sB + (64 + g) * BSTR + ks * 32 + q4 * 4;
                        uint32_t b8[2] = { *(const uint32_t*)bs, *(const uint32_t*)(bs + 16) };
                        MMA16816(d, Af[ks], b8);
                    }
                    s1a = d[0]; s1b = d[2];   // col 64 on q4==0; exactly 0 elsewhere
                }
            }

            // GEMM2: score = relu(hid) @ at_h ; D-frag -> A-frag, same thread
            float dd[4] = {0.f, 0.f, 0.f, 0.f};
            #pragma unroll
            for (int ks = 0; ks < 4; ks++) {
                uint32_t A2[4] = { hp[2 * ks][0], hp[2 * ks][1],
                                   hp[2 * ks + 1][0], hp[2 * ks + 1][1] };
                MMA16816(dd, A2, Bh[ks]);
            }
            acc = fmaf(dd[0], s1a, fmaf(dd[2], s1b, acc));  // zero off q4==0/col0
        }
        accv[nb] = acc;
    }

    #pragma unroll
    for (int nb = 0; nb < NBATCH; nb++) {
        float r = accv[nb];
        #pragma unroll
        for (int off = 16; off; off >>= 1) r += __shfl_xor_sync(0xffffffffu, r, off);
        if (lane == 0) sTot[nb][w] = r;
    }
    __syncthreads();
    if (tid < NBATCH) {
        float t = sFm1[tid];
        #pragma unroll
        for (int k = 0; k < 8; k++) t += sTot[tid][k];
        out[b0 + tid] = 1.f / (1.f + expf(-t));
    }
}

extern "C" void kernel_launch(void* const* d_in, const int* in_sizes, int n_in,
                              void* d_out, int out_size)
{
    (void)in_sizes; (void)n_in; (void)out_size;
    afm_dual_kernel<<<BSZ / NBATCH, NTHR>>>(
        (const int*)  d_in[0],   // x      [F, B]
        (const float*)d_in[1],   // emb_v  [VOCAB, K]
        (const float*)d_in[2],   // at_w   [K, H]
        (const float*)d_in[3],   // at_b   [H]
        (const float*)d_in[4],   // at_h   [H, 1]
        (const float*)d_in[5],   // p      [K, 1]
        (const float*)d_in[6],   // w0     scalar
        (const float*)d_in[7],   // w1     [VOCAB, 1]
        (float*)d_out);
}

// round 8
// speedup vs baseline: 6.8086x; 1.2142x over previous
#include <cuda_runtime.h>
#include <cuda_bf16.h>
#include <cstdint>
#include <math.h>

// AFM fused dual-GEMM kernel, bf16 V (mma.sync m16n8k16, plain-sm_103 PTX).
//
// GEMM1: D = VV[16p x 64] @ B^T, B = [W^T(64); p(1); 0(7)] -> N=72
//        D[:,0:64] = hid pre-act (fp32), D[:,64] = s1 = VV.p (fp32)
// GEMM2: score = relu(D+bias) @ at_h   (D-frag -> A-frag, same thread, 0 shuffles)
// acc  += score_g * s1_g   (only q4==0 lanes nonzero)
// out[b] = sigmoid(acc_sum + w0 + sum w1[x[:,b]])   (fm1 exact fp32 - dominates)
//
// V stored as bf16 in smem: A-frags built with 2 LDS.32 + 1 mul.rn.bf16x2 each
// (halves crossbar bytes, kills the FMUL/PACK construction chain of R5).

#define F      32
#define BSZ    2048
#define KD     64
#define NPAIR  496
#define NPAD   512
#define NTHR   256
#define NBATCH 2
#define BSTR   144          // sB row stride (bytes)
#define VROW   72           // sV row stride in bf16 (=144B = 36 words: conflict-free)
#define VNB    (33 * VROW)  // per-batch bf16 count (32 fields + 1 zero row)

#define MMA16816(d, a, bb)                                                      \
    asm volatile("mma.sync.aligned.m16n8k16.row.col.f32.bf16.bf16.f32 "         \
                 "{%0,%1,%2,%3}, {%4,%5,%6,%7}, {%8,%9}, {%0,%1,%2,%3};"        \
                 : "+f"((d)[0]), "+f"((d)[1]), "+f"((d)[2]), "+f"((d)[3])       \
                 : "r"((a)[0]), "r"((a)[1]), "r"((a)[2]), "r"((a)[3]),          \
                   "r"((bb)[0]), "r"((bb)[1]))

// pack two fp32 -> bf16x2 (flo -> low half)
#define PACKBF2(res, flo, fhi) \
    asm("cvt.rn.bf16x2.f32 %0, %1, %2;" : "=r"(res) : "f"(fhi), "f"(flo))
#define HMUL2(res, a, b) \
    asm("mul.rn.bf16x2 %0, %1, %2;" : "=r"(res) : "r"(a), "r"(b))

__global__ __launch_bounds__(NTHR, 2)
void afm_bf16_kernel(const int* __restrict__ x, const float* __restrict__ emb_v,
                     const float* __restrict__ at_w, const float* __restrict__ at_b,
                     const float* __restrict__ at_h, const float* __restrict__ p,
                     const float* __restrict__ w0, const float* __restrict__ w1,
                     float* __restrict__ out)
{
    __shared__ __align__(16) __nv_bfloat16 sVb[NBATCH * VNB];   // ~9.3 KB
    __shared__ __align__(16) unsigned char sB[72 * BSTR];       // ~10 KB
    __shared__ float sBias[KD];
    __shared__ int   sPair[NPAD];
    __shared__ int   sX[NBATCH][F];
    __shared__ float sTot[NBATCH][8];
    __shared__ float sFm1[NBATCH];

    const int b0 = blockIdx.x * NBATCH, tid = threadIdx.x;
    const int w = tid >> 5, lane = tid & 31;
    const int g = lane >> 2, q4 = lane & 3;

    if (tid < NBATCH * F) sX[tid >> 5][tid & 31] = x[(tid & 31) * BSZ + b0 + (tid >> 5)];
    __syncthreads();

    // V gather: float4 from gmem -> 2x bf16x2 -> uint2 store (row stride 144B)
    for (int idx = tid; idx < NBATCH * F * 16; idx += NTHR) {
        const int nb = idx >> 9, rem = idx & 511, f = rem >> 4, c = rem & 15;
        const float4 v = ((const float4*)(emb_v + (size_t)sX[nb][f] * KD))[c];
        uint32_t p0, p1;
        PACKBF2(p0, v.x, v.y);
        PACKBF2(p1, v.z, v.w);
        ((uint2*)(sVb + nb * VNB))[f * 18 + c] = make_uint2(p0, p1);
    }
    if (tid < NBATCH * 18)   // zero row (index 32) per batch
        ((uint2*)(sVb + (tid / 18) * VNB))[32 * 18 + (tid % 18)] = make_uint2(0u, 0u);

    // sB rows 0..63 = W^T, row 64 = p, rows 65..71 = 0
    for (int idx = tid; idx < KD * KD; idx += NTHR) {
        const int k = idx >> 6, h = idx & 63;
        *(__nv_bfloat16*)(sB + h * BSTR + k * 2) = __float2bfloat16(at_w[idx]);
    }
    if (tid < KD) *(__nv_bfloat16*)(sB + 64 * BSTR + tid * 2) = __float2bfloat16(p[tid]);
    for (int idx = tid; idx < 7 * (BSTR / 4); idx += NTHR) {
        const int row = 65 + idx / (BSTR / 4), c = idx % (BSTR / 4);
        *(uint32_t*)(sB + row * BSTR + c * 4) = 0u;
    }
    if (tid < KD) sBias[tid] = at_b[tid];
    for (int q = tid; q < NPAD; q += NTHR) {
        if (q < NPAIR) {
            int i = 0, r = q;
            while (r >= F - 1 - i) { r -= F - 1 - i; i++; }
            sPair[q] = (i << 8) | (i + 1 + r);
        } else sPair[q] = (32 << 8) | 32;     // dummy -> zero VV -> s1=0
    }
    if (w >= 8 - NBATCH) {                    // fm1 exact fp32 (dominates logit)
        const int nb = 7 - w;
        float v = w1[sX[nb][lane]];
        #pragma unroll
        for (int off = 16; off; off >>= 1) v += __shfl_xor_sync(0xffffffffu, v, off);
        if (lane == 0) sFm1[nb] = v + w0[0];
    }
    __syncthreads();

    // GEMM1 B fragments in registers (held across both batches)
    uint32_t Bf[8][4][2];
    #pragma unroll
    for (int nt = 0; nt < 8; nt++)
        #pragma unroll
        for (int ks = 0; ks < 4; ks++) {
            const unsigned char* base = sB + (nt * 8 + g) * BSTR + ks * 32 + q4 * 4;
            Bf[nt][ks][0] = *(const uint32_t*)(base);
            Bf[nt][ks][1] = *(const uint32_t*)(base + 16);
        }
    // GEMM2 B fragments: col 0 = at_h, cols 1..7 = 0
    uint32_t Bh[4][2];
    #pragma unroll
    for (int ks = 0; ks < 4; ks++) {
        if (g == 0) {
            const int k0 = ks * 16 + 2 * q4;
            PACKBF2(Bh[ks][0], at_h[k0], at_h[k0 + 1]);
            PACKBF2(Bh[ks][1], at_h[k0 + 8], at_h[k0 + 9]);
        } else { Bh[ks][0] = 0u; Bh[ks][1] = 0u; }
    }

    float accv[NBATCH];
    #pragma unroll 1
    for (int nb = 0; nb < NBATCH; nb++) {
        const __nv_bfloat16* sVn = sVb + nb * VNB;
        float acc = 0.f;
        #pragma unroll
        for (int mt = 0; mt < 4; mt++) {
            const int q0 = w * 64 + mt * 16 + g;
            const int pr0 = sPair[q0], pr1 = sPair[q0 + 8];
            const uint32_t* pi0 = (const uint32_t*)(sVn + (pr0 >> 8) * VROW);
            const uint32_t* pj0 = (const uint32_t*)(sVn + (pr0 & 255) * VROW);
            const uint32_t* pi1 = (const uint32_t*)(sVn + (pr1 >> 8) * VROW);
            const uint32_t* pj1 = (const uint32_t*)(sVn + (pr1 & 255) * VROW);

            // A fragments: 2 LDS.32 + 1 HMUL2 each (word idx 8ks+q4, +4 for k+8)
            uint32_t Af[4][4];
            #pragma unroll
            for (int ks = 0; ks < 4; ks++) {
                const int u = 8 * ks + q4;
                HMUL2(Af[ks][0], pi0[u],     pj0[u]);
                HMUL2(Af[ks][1], pi1[u],     pj1[u]);
                HMUL2(Af[ks][2], pi0[u + 4], pj0[u + 4]);
                HMUL2(Af[ks][3], pi1[u + 4], pj1[u + 4]);
            }

            // GEMM1: hid (nt 0..7) + s1 (nt 8, B-frag streamed from smem)
            uint32_t hp[8][2];
            float s1a = 0.f, s1b = 0.f;
            #pragma unroll
            for (int nt = 0; nt < 9; nt++) {
                float d[4] = {0.f, 0.f, 0.f, 0.f};
                if (nt < 8) {
                    #pragma unroll
                    for (int ks = 0; ks < 4; ks++) MMA16816(d, Af[ks], Bf[nt][ks]);
                    const float2 bc = *(const float2*)(sBias + nt * 8 + 2 * q4);
                    const float d0 = fmaxf(d[0] + bc.x, 0.f), d1 = fmaxf(d[1] + bc.y, 0.f);
                    const float d2 = fmaxf(d[2] + bc.x, 0.f), d3 = fmaxf(d[3] + bc.y, 0.f);
                    PACKBF2(hp[nt][0], d0, d1);
                    PACKBF2(hp[nt][1], d2, d3);
                } else {
                    #pragma unroll
                    for (int ks = 0; ks < 4; ks++) {
                        const unsigned char* bs = sB + (64 + g) * BSTR + ks * 32 + q4 * 4;
                        uint32_t b8[2] = { *(const uint32_t*)bs, *(const uint32_t*)(bs + 16) };
                        MMA16816(d, Af[ks], b8);
                    }
                    s1a = d[0]; s1b = d[2];   // col 64 on q4==0; exactly 0 elsewhere
                }
            }

            // GEMM2: score = relu(hid) @ at_h ; D-frag -> A-frag, same thread
            float dd[4] = {0.f, 0.f, 0.f, 0.f};
            #pragma unroll
            for (int ks = 0; ks < 4; ks++) {
                uint32_t A2[4] = { hp[2 * ks][0], hp[2 * ks][1],
                                   hp[2 * ks + 1][0], hp[2 * ks + 1][1] };
                MMA16816(dd, A2, Bh[ks]);
            }
            acc = fmaf(dd[0], s1a, fmaf(dd[2], s1b, acc));  // zero off q4==0/col0
        }
        accv[nb] = acc;
    }

    #pragma unroll
    for (int nb = 0; nb < NBATCH; nb++) {
        float r = accv[nb];
        #pragma unroll
        for (int off = 16; off; off >>= 1) r += __shfl_xor_sync(0xffffffffu, r, off);
        if (lane == 0) sTot[nb][w] = r;
    }
    __syncthreads();
    if (tid < NBATCH) {
        float t = sFm1[tid];
        #pragma unroll
        for (int k = 0; k < 8; k++) t += sTot[tid][k];
        out[b0 + tid] = 1.f / (1.f + expf(-t));
    }
}

extern "C" void kernel_launch(void* const* d_in, const int* in_sizes, int n_in,
                              void* d_out, int out_size)
{
    (void)in_sizes; (void)n_in; (void)out_size;
    afm_bf16_kernel<<<BSZ / NBATCH, NTHR>>>(
        (const int*)  d_in[0],   // x      [F, B]
        (const float*)d_in[1],   // emb_v  [VOCAB, K]
        (const float*)d_in[2],   // at_w   [K, H]
        (const float*)d_in[3],   // at_b   [H]
        (const float*)d_in[4],   // at_h   [H, 1]
        (const float*)d_in[5],   // p      [K, 1]
        (const float*)d_in[6],   // w0     scalar
        (const float*)d_in[7],   // w1     [VOCAB, 1]
        (float*)d_out);
}